// round 9
// baseline (speedup 1.0000x reference)
#include <cuda_runtime.h>

// LoCon1d: out[b][o][s] = sum_{c,k} in[b][c][s+k-1] * w[o][c][s][k] + bias[o][s]
// B=16, Cin=64, Cout=64, S=1024, K=3 (zero pad)
//
// Two kernels:
//  1) transpose_kernel: input (B,C,S) -> g_trans[c][1+s][b] with zeroed halo rows
//  2) locon1d_kernel:   weight + transposed-input both streamed via cp.async ring

#define S_LEN   1024
#define CIN     64
#define COUT    64
#define BATCH   16
#define KW      3
#define S_TILE  16
#define O_TILE  16
#define HALO    (S_TILE + 2)        // 18
#define THREADS 256

// transposed input: [c][j=0..1025][b=0..15], j = s+1 (rows 0 and 1025 are zero)
#define TR_J    (S_LEN + 2)
__device__ float g_trans[CIN * TR_J * BATCH];

// ring stage: weight 16o*16s*3k floats = 3072B, input 18j * 5 float4 = 1440B
#define W_STAGE_F4   192
#define IN_STAGE_F4  90
#define STAGE_BYTES  4608            // 3072 + 1440, padded to 128B multiple
#define N_STAGES     8
#define SMEM_BYTES   (N_STAGES * STAGE_BYTES)   // 36864

typedef unsigned long long u64;

__device__ __forceinline__ u64 splat2(float w) {
    u64 r;
    asm("mov.b64 %0, {%1, %1};" : "=l"(r) : "f"(w));
    return r;
}
__device__ __forceinline__ void fma2(u64 &d, u64 a, u64 b) {
    asm("fma.rn.f32x2 %0, %1, %2, %0;" : "+l"(d) : "l"(a), "l"(b));
}
__device__ __forceinline__ float2 u2f(u64 u) {
    float2 r;
    asm("mov.b64 {%0, %1}, %2;" : "=f"(r.x), "=f"(r.y) : "l"(u));
    return r;
}
__device__ __forceinline__ void cp16(unsigned dst, const void* src) {
    asm volatile("cp.async.cg.shared.global [%0], [%1], 16;" :: "r"(dst), "l"(src));
}
__device__ __forceinline__ void cp_commit() {
    asm volatile("cp.async.commit_group;");
}
__device__ __forceinline__ void cp_wait6() {
    asm volatile("cp.async.wait_group 6;");
}

#define WF(warr, i) (((i) & 3) == 0 ? (warr)[(i) >> 2].x : \
                     ((i) & 3) == 1 ? (warr)[(i) >> 2].y : \
                     ((i) & 3) == 2 ? (warr)[(i) >> 2].z : (warr)[(i) >> 2].w)

// ---------------------------------------------------------------------------
// transpose: input[b][c][s] -> g_trans[c][1+s][b]; zero rows j=0 and j=1025
// grid (64 c, 16 s-chunks of 64), block 256
// ---------------------------------------------------------------------------
__global__ void __launch_bounds__(256)
transpose_kernel(const float* __restrict__ input)
{
    __shared__ float tile[BATCH][65];   // 65 pad kills write-phase bank conflicts

    const int c  = blockIdx.x;
    const int s0 = blockIdx.y * 64;
    const int tid = threadIdx.x;

    // load: 16b x 64s, s-fastest (coalesced 256B per warp)
    #pragma unroll
    for (int r = 0; r < 4; ++r) {
        const int idx = tid + r * 256;          // 0..1023
        const int b  = idx >> 6;
        const int sl = idx & 63;
        tile[b][sl] = input[((size_t)b * CIN + c) * S_LEN + s0 + sl];
    }
    __syncthreads();

    // store: b-fastest (128B contiguous per warp)
    #pragma unroll
    for (int r = 0; r < 4; ++r) {
        const int idx = tid + r * 256;
        const int b  = idx & 15;
        const int sl = idx >> 4;                // 0..63
        g_trans[((size_t)c * TR_J + 1 + s0 + sl) * BATCH + b] = tile[b][sl];
    }

    // zero halo rows (block 0 only; conv runs in a later kernel, order safe)
    if (blockIdx.x == 0 && blockIdx.y == 0) {
        for (int e = tid; e < CIN * BATCH; e += 256) {
            const int cc = e >> 4, bb = e & 15;
            g_trans[((size_t)cc * TR_J + 0) * BATCH + bb]          = 0.f;
            g_trans[((size_t)cc * TR_J + TR_J - 1) * BATCH + bb]   = 0.f;
        }
    }
}

// ---------------------------------------------------------------------------
// main conv
// ---------------------------------------------------------------------------
__global__ void __launch_bounds__(THREADS, 3)
locon1d_kernel(const float* __restrict__ weight,
               const float* __restrict__ bias,
               float* __restrict__ out)
{
    extern __shared__ float4 sh4[];

    const int s0 = blockIdx.x * S_TILE;
    const int o0 = blockIdx.y * O_TILE;
    const int tid = threadIdx.x;
    const unsigned sh_u = (unsigned)__cvta_generic_to_shared(sh4);

    // ---- cp.async source pointers (fixed per thread) ----------------------
    // weight part: tid < 192: f=tid: o=f/12, rem=f%12
    //   src(c) = weight + ((o0+o)*CIN + c)*3072 + s0*3 + rem*4   [floats]
    // input part: tid >= 184: f=tid-184 (0..71): j=f/4, bq=f%4
    //   src(c) = g_trans + (c*TR_J + s0 + j)*16 + bq*4           [floats]
    const int wf_ = tid;
    const float* wsrc = weight + ((size_t)(o0 + wf_ / 12) * CIN) * (S_LEN * 3)
                               + (size_t)s0 * 3 + (wf_ % 12) * 4;
    const int inf = tid - 184;                   // valid for tid>=184
    const float* isrc = g_trans + ((size_t)(s0 + (inf < 0 ? 0 : inf / 4))) * BATCH
                               + (inf < 0 ? 0 : (inf % 4)) * 4;
    const unsigned wdst_off = (unsigned)(wf_ * 16);
    const unsigned idst_off = (unsigned)(3072 + (inf < 0 ? 0
                               : (5 * (inf / 4) + (inf % 4)) * 16));

    auto WISSUE = [&](int c) {
        const unsigned stg = sh_u + (unsigned)((c & (N_STAGES - 1)) * STAGE_BYTES);
        if (tid < W_STAGE_F4)
            cp16(stg + wdst_off, wsrc + (size_t)c * (S_LEN * 3));
        if (tid >= 184)
            cp16(stg + idst_off, isrc + (size_t)c * (TR_J * BATCH));
        cp_commit();
    };

    // prologue: 7 stages in flight.
    // Group math (the R7 bug was here): before iter-c wait, commits = 7+c;
    // wait_group 6 -> completed >= c+1 -> group c (stage c) IS resident.
    WISSUE(0); WISSUE(1); WISSUE(2); WISSUE(3); WISSUE(4); WISSUE(5); WISSUE(6);

    // ---- thread mapping ---------------------------------------------------
    const int bg = tid & 3;             // 4 batches each (one float4 column)
    const int sg = (tid >> 2) & 3;      // 4 s each
    const int ow = tid >> 4;            // 0..15, one cout each
    const int o     = o0 + ow;
    const int sbase = s0 + sg * 4;

    const int wofs = ow * 12 + 3 * sg;          // float4 idx in weight part
    const int vofs = 5 * (4 * sg) + bg;         // float4 idx in input part (+5 per d)

    u64 acc[4][2];
    #pragma unroll
    for (int j = 0; j < 4; ++j) { acc[j][0] = 0ull; acc[j][1] = 0ull; }

    for (int c = 0; c < CIN; ++c) {
        cp_wait6();          // stage c (group c) resident for MY cp16s
        __syncthreads();     // everyone's waited -> stage c fully visible;
                             // also releases slot (c-1)&7 for the refill below

        const float4* stg = sh4 + (c & (N_STAGES - 1)) * (STAGE_BYTES / 16);
        float4 wa[3];
        #pragma unroll
        for (int i = 0; i < 3; ++i)
            wa[i] = stg[wofs + i];

        const ulonglong2* vstg =
            reinterpret_cast<const ulonglong2*>(stg + W_STAGE_F4);
        ulonglong2 v[6];
        #pragma unroll
        for (int d = 0; d < 6; ++d)
            v[d] = vstg[vofs + 5 * d];

        #pragma unroll
        for (int ss = 0; ss < 4; ++ss) {
            #pragma unroll
            for (int k = 0; k < KW; ++k) {
                const int d  = ss + k;          // 0..5
                const int wi = ss * 3 + k;      // 0..11
                const u64 w2 = splat2(WF(wa, wi));
                fma2(acc[ss][0], v[d].x, w2);
                fma2(acc[ss][1], v[d].y, w2);
            }
        }

        // refill stage c+7 -> slot (c+7)&7 == (c-1)&7, freed by this iter's
        // barrier. Readers hold slot c&7; in-flight stage c+6 writes (c-2)&7.
        // All disjoint. Empty commit keeps group numbering exact in the tail.
        if (c + 7 < CIN) WISSUE(c + 7); else cp_commit();
    }

    // ---- epilogue: bias + store ------------------------------------------
    {
        const float4 bz = *reinterpret_cast<const float4*>(bias + (size_t)o * S_LEN + sbase);
        #pragma unroll
        for (int pr = 0; pr < 2; ++pr) {
            const float2 f0 = u2f(acc[0][pr]);
            const float2 f1 = u2f(acc[1][pr]);
            const float2 f2 = u2f(acc[2][pr]);
            const float2 f3 = u2f(acc[3][pr]);
            const int b0 = bg * 4 + pr * 2;
            float4 r0 = make_float4(f0.x + bz.x, f1.x + bz.y, f2.x + bz.z, f3.x + bz.w);
            float4 r1 = make_float4(f0.y + bz.x, f1.y + bz.y, f2.y + bz.z, f3.y + bz.w);
            *reinterpret_cast<float4*>(out + ((size_t)(b0 * COUT + o)) * S_LEN + sbase) = r0;
            *reinterpret_cast<float4*>(out + ((size_t)((b0 + 1) * COUT + o)) * S_LEN + sbase) = r1;
        }
    }
}

extern "C" void kernel_launch(void* const* d_in, const int* in_sizes, int n_in,
                              void* d_out, int out_size) {
    const float* input  = (const float*)d_in[0];
    const float* weight = (const float*)d_in[1];
    const float* bias   = (const float*)d_in[2];
    float* out = (float*)d_out;

    cudaFuncSetAttribute(locon1d_kernel,
                         cudaFuncAttributeMaxDynamicSharedMemorySize, SMEM_BYTES);

    dim3 tgrid(CIN, S_LEN / 64);                 // (64, 16)
    transpose_kernel<<<tgrid, 256>>>(input);

    dim3 grid(S_LEN / S_TILE, COUT / O_TILE);    // (64, 4)
    locon1d_kernel<<<grid, THREADS, SMEM_BYTES>>>(weight, bias, out);
}